// round 15
// baseline (speedup 1.0000x reference)
#include <cuda_runtime.h>
#include <cuda_bf16.h>

// ---------------------------------------------------------------------------
// B=4 batches, M=256 bins, N = in_sizes[0]/B particles.
// joint[b,i,j] = sum_n exp(-0.5((x-bins[i])/h)^2) * exp(-0.5((y-bins[j])/h)^2)
// out = joint / (sum_ij joint + 1e-10), h = bins[1]-bins[0].
//
// fp32 Gaussian support: term == 0 once |d|/h > 14.4 -> banded. Particles are
// pre-binned into per-(batch,tile) buckets (cut 14.6h, exact w.r.t. fp32
// underflow). Buckets 8-way segmented (128B-strided counters, no L2 atomic
// serialization). tile_kernel is WARP-SPECIALIZED: warps 0-3 produce kx/ky
// tables (MUFU) into a double buffer; warps 4-7 consume (FMA/LDS) with 4x8
// register blocking. full/empty named barriers overlap the two pipes.
// ---------------------------------------------------------------------------

#define NBATCH 4
#define MDIM   256
#define TILE   16
#define NT     16        // tiles per axis
#define SPLIT  8         // segments per bucket == split CTAs per bucket
#define SEGCAP 2048      // per-segment capacity (hot segment ~1k expected)
#define PBUF   128       // particles per pipeline chunk (per buffer)
#define CPAD   20        // 16 table entries + 4 pad floats
#define NBUCK  (NBATCH * NT * NT)

// Named barrier ids: full[buf] = 1+buf, empty[buf] = 3+buf.
#define BAR_SYNC(id)   asm volatile("bar.sync %0, 256;"   :: "r"(id) : "memory")
#define BAR_ARRIVE(id) asm volatile("bar.arrive %0, 256;" :: "r"(id) : "memory")

// Static scratch (load-time allocation; no runtime alloc).
__device__ float2 g_bucket[NBUCK * SPLIT * SEGCAP];        // ~134 MB
__device__ int    g_cnt[NBUCK * SPLIT * 32];               // 128B-strided ctrs
__device__ float  g_part[NBATCH * SPLIT * MDIM * MDIM];    // 8 MB partials
__device__ float  g_sum[NBATCH];
__device__ int    g_done;

__device__ __forceinline__ float ex2f(float a) {
    float r;
    asm("ex2.approx.ftz.f32 %0, %1;" : "=f"(r) : "f"(a));
    return r;
}

// ---------------------------------------------------------------------------
__global__ void zero_kernel()
{
    const int t = blockIdx.x * 256 + threadIdx.x;
    if (t < NBUCK * SPLIT) g_cnt[t * 32] = 0;
    if (t < NBATCH)        g_sum[t] = 0.f;
    if (t == NBATCH)       g_done = 0;
}

// ---------------------------------------------------------------------------
// One thread per particle: scatter (x,y) into every tile bucket whose window
// contains it (<=3x3 tiles). Tile i window (bin units t=(x-b0)/h):
//   i in [ceil((t-29.6)/16), floor((t+14.6)/16)].
__global__ void bin_kernel(const float* __restrict__ x,
                           const float* __restrict__ y,
                           const float* __restrict__ bins, int N)
{
    const int idx = blockIdx.x * 256 + threadIdx.x;
    const int b   = blockIdx.y;
    if (idx >= N) return;

    const float b0   = __ldg(bins);
    const float h    = __ldg(bins + 1) - b0;
    const float invh = 1.0f / h;

    const float xv = __ldg(x + b * N + idx);
    const float yv = __ldg(y + b * N + idx);
    const float tx = (xv - b0) * invh;
    const float ty = (yv - b0) * invh;

    const float s = 1.0f / 16.0f;
    const int ix0 = max(0,      (int)ceilf ((tx - 29.6f) * s));
    const int ix1 = min(NT - 1, (int)floorf((tx + 14.6f) * s));
    const int iy0 = max(0,      (int)ceilf ((ty - 29.6f) * s));
    const int iy1 = min(NT - 1, (int)floorf((ty + 14.6f) * s));

    const int seg = (threadIdx.x >> 5) & (SPLIT - 1);
    const float2 v = make_float2(xv, yv);
    for (int i = ix0; i <= ix1; i++)
        for (int j = iy0; j <= iy1; j++) {
            const int id2 = (((b * NT + i) * NT + j) * SPLIT) + seg;
            const int pos = atomicAdd(&g_cnt[id2 * 32], 1);
            if (pos < SEGCAP) g_bucket[(size_t)id2 * SEGCAP + pos] = v;
        }
}

// ---------------------------------------------------------------------------
// CTA (ti, tj, b*SPLIT+s): warp-specialized banded accumulation.
//   Producers (tid 0..127): per chunk, thread tid owns particle base+tid;
//     computes 16 kx + 16 ky table entries (MUFU ex2, float4 STS) into
//     buffer (m&1). Guarded by empty[m&1] (skipped for m<2), signals
//     full[m&1] with bar.arrive.
//   Consumers (tid 128..255): 16 replicas x 8 subs; each thread owns a 4x4x2
//     (4 i x 8 j) register block. Waits full[m&1], accumulates particles
//     p == rrep (mod 16), signals empty[m&1].
__global__ void __launch_bounds__(256, 4)
tile_kernel(const float* __restrict__ bins)
{
    __shared__ float sbx[TILE], sby[TILE];
    __shared__ float kxT[2 * PBUF * CPAD];   // double-buffered tables
    __shared__ float kyT[2 * PBUF * CPAD];

    const int tid = threadIdx.x;
    const int ti  = blockIdx.x;
    const int tj  = blockIdx.y;
    const int b   = blockIdx.z >> 3;     // z = b*SPLIT + s
    const int s   = blockIdx.z & (SPLIT - 1);
    const int i0  = ti * TILE;
    const int j0  = tj * TILE;

    if (tid < TILE)            sbx[tid]        = bins[i0 + tid];
    else if (tid < 2 * TILE)   sby[tid - TILE] = bins[j0 + (tid - TILE)];
    __syncthreads();

    const float h    = bins[1] - bins[0];
    const float cexp = -0.72134752044f / (h * h);   // -0.5*log2(e)/h^2

    const int id2 = (((b * NT + ti) * NT + tj) * SPLIT) + s;
    const int c   = min(g_cnt[id2 * 32], SEGCAP);
    const int nch = (c + PBUF - 1) / PBUF;
    const float2* __restrict__ bk = g_bucket + (size_t)id2 * SEGCAP;

    float acc[4][8];
#pragma unroll
    for (int a = 0; a < 4; a++)
#pragma unroll
        for (int e = 0; e < 8; e++) acc[a][e] = 0.f;

    if (tid < 128) {
        // ---------------- producer ----------------
        float2 nv = make_float2(0.f, 0.f);
        if (tid < c) nv = __ldg(bk + tid);

        for (int m = 0; m < nch; m++) {
            const int buf = m & 1;
            const float2 v = nv;
            const int nxt = (m + 1) * PBUF + tid;
            if (nxt < c) nv = __ldg(bk + nxt);       // prefetch next chunk

            if (m >= 2) BAR_SYNC(3 + buf);           // wait buffer free

            const int cc = min(PBUF, c - m * PBUF);
            if (tid < cc) {
                float* rx = kxT + (buf * PBUF + tid) * CPAD;
                float* ry = kyT + (buf * PBUF + tid) * CPAD;
#pragma unroll
                for (int k0 = 0; k0 < TILE; k0 += 4) {
                    float4 a4, e4;
                    float d;
                    d = v.x - sbx[k0 + 0]; a4.x = ex2f(cexp * d * d);
                    d = v.x - sbx[k0 + 1]; a4.y = ex2f(cexp * d * d);
                    d = v.x - sbx[k0 + 2]; a4.z = ex2f(cexp * d * d);
                    d = v.x - sbx[k0 + 3]; a4.w = ex2f(cexp * d * d);
                    d = v.y - sby[k0 + 0]; e4.x = ex2f(cexp * d * d);
                    d = v.y - sby[k0 + 1]; e4.y = ex2f(cexp * d * d);
                    d = v.y - sby[k0 + 2]; e4.z = ex2f(cexp * d * d);
                    d = v.y - sby[k0 + 3]; e4.w = ex2f(cexp * d * d);
                    *(float4*)(rx + k0) = a4;
                    *(float4*)(ry + k0) = e4;
                }
            }
            BAR_ARRIVE(1 + buf);                     // signal buffer full
        }
    } else {
        // ---------------- consumer ----------------
        const int ctid = tid - 128;
        const int sub  = ctid & 7;
        const int rrep = ctid >> 3;                  // 0..15
        const int bi4  = (sub & 3) * 4;              // i offset (4 rows)
        const int bj8  = (sub >> 2) * 8;             // j offset (8 cols)

        for (int m = 0; m < nch; m++) {
            const int buf = m & 1;
            BAR_SYNC(1 + buf);                       // wait buffer full

            const int cc = min(PBUF, c - m * PBUF);
            const float* kxB = kxT + buf * PBUF * CPAD;
            const float* kyB = kyT + buf * PBUF * CPAD;
            for (int p = rrep; p < cc; p += 16) {
                const float4 kx  = *(const float4*)(kxB + p * CPAD + bi4);
                const float4 ky0 = *(const float4*)(kyB + p * CPAD + bj8);
                const float4 ky1 = *(const float4*)(kyB + p * CPAD + bj8 + 4);
                const float kxa[4] = {kx.x, kx.y, kx.z, kx.w};
                const float kya[8] = {ky0.x, ky0.y, ky0.z, ky0.w,
                                      ky1.x, ky1.y, ky1.z, ky1.w};
#pragma unroll
                for (int a = 0; a < 4; a++)
#pragma unroll
                    for (int e = 0; e < 8; e++)
                        acc[a][e] += kxa[a] * kya[e];
            }
            BAR_ARRIVE(3 + buf);                     // signal buffer free
        }
    }

    __syncthreads();   // rejoin; table buffers now reusable as scratch

    // Consumers dump 16-replica partials (fixed order -> deterministic).
    float* red = kxT;                                // 16*256 floats = 16 KB
    if (tid >= 128) {
        const int ctid = tid - 128;
        const int sub  = ctid & 7;
        const int rrep = ctid >> 3;
#pragma unroll
        for (int a = 0; a < 4; a++)
#pragma unroll
            for (int e = 0; e < 8; e++)
                red[rrep * 256 + sub * 32 + a * 8 + e] = acc[a][e];
    }
    __syncthreads();

    // All 256 threads: one output element each, sum over 16 replicas.
    const int oi   = tid >> 4;
    const int oj   = tid & 15;
    const int sub2 = (oi >> 2) | ((oj >> 3) << 2);
    const int q2   = (oi & 3) * 8 + (oj & 7);
    float v = 0.f;
#pragma unroll
    for (int rr = 0; rr < 16; rr++)
        v += red[rr * 256 + sub2 * 32 + q2];

    g_part[((b * SPLIT + s) * MDIM + (i0 + oi)) * MDIM + (j0 + oj)] = v;
}

// ---------------------------------------------------------------------------
// Fused reduce + normalize. 256 CTAs x 256 threads (all co-resident; 32 regs
// / 1KB smem -> far more resident slots than 256 CTAs, spin terminates).
__global__ void reduce_norm_kernel(float* __restrict__ out)
{
    const int t  = blockIdx.x * 256 + threadIdx.x;   // float4 index
    const int b  = (t * 4) / (MDIM * MDIM);
    const int ij = t - b * (MDIM * MDIM / 4);

    float4 v = make_float4(0.f, 0.f, 0.f, 0.f);
#pragma unroll
    for (int s = 0; s < SPLIT; s++) {
        const float4 p = ((const float4*)g_part)[(b * SPLIT + s) *
                                                 (MDIM * MDIM / 4) + ij];
        v.x += p.x; v.y += p.y; v.z += p.z; v.w += p.w;
    }

    __shared__ float sm[256];
    sm[threadIdx.x] = (v.x + v.y) + (v.z + v.w);
    __syncthreads();
    for (int off = 128; off > 0; off >>= 1) {
        if (threadIdx.x < off) sm[threadIdx.x] += sm[threadIdx.x + off];
        __syncthreads();
    }
    if (threadIdx.x == 0) {
        atomicAdd(&g_sum[b], sm[0]);
        __threadfence();                       // release g_sum before arrive
        atomicAdd(&g_done, 1);
        while (*(volatile int*)&g_done < (int)gridDim.x) { }
    }
    __syncthreads();

    const float sv  = *(volatile float*)&g_sum[b];
    const float inv = 1.0f / (sv + 1e-10f);
    v.x *= inv; v.y *= inv; v.z *= inv; v.w *= inv;
    ((float4*)out)[t] = v;
}

// ---------------------------------------------------------------------------
extern "C" void kernel_launch(void* const* d_in, const int* in_sizes, int n_in,
                              void* d_out, int out_size)
{
    const float* x    = (const float*)d_in[0];   // (B, N) f32
    const float* y    = (const float*)d_in[1];   // (B, N) f32
    const float* bins = (const float*)d_in[2];   // (M,)  f32

    const int N = in_sizes[0] / NBATCH;

    zero_kernel<<<(NBUCK * SPLIT + 255) / 256, 256>>>();

    dim3 bgrid((N + 255) / 256, NBATCH);
    bin_kernel<<<bgrid, 256>>>(x, y, bins, N);

    dim3 tgrid(NT, NT, NBATCH * SPLIT);
    tile_kernel<<<tgrid, 256>>>(bins);

    reduce_norm_kernel<<<NBATCH * MDIM * MDIM / 1024, 256>>>((float*)d_out);
}